// round 8
// baseline (speedup 1.0000x reference)
#include <cuda_runtime.h>
#include <cstdint>

// RationalsModel: out[i] = P(x[i]) / (|x[i] * Q(x[i])| + 1)
//   P = sum_{p=0}^{63} coef[p]      * x^p
//   Q = sum_{p=0}^{63} coef[64 + p] * x^p
//
// R8: all rounds so far are RF-banking-bound: FFMA2 reads 3 register pairs
// (3 even + 3 odd distinct) -> rt=3. R7's gain was pure DVFS (2.0 vs 1.73GHz),
// still rt=3. This round targets the operand REUSE cache: group the 4 FMAs
// sharing coefficient cn back-to-back (then 4 sharing cm, reversed so xp[3]
// also chains) -> slot-3 .reuse removes the coefficient from the bank count
// for 3 of 4 FFMA2s -> blended rt~2.25. asm volatile pins the ordering.

__device__ __forceinline__ uint64_t pack2(float lo, float hi) {
    uint64_t r;
    asm("mov.b64 %0, {%1, %2};" : "=l"(r) : "f"(lo), "f"(hi));
    return r;
}

__device__ __forceinline__ void unpack2(uint64_t v, float& lo, float& hi) {
    asm("mov.b64 {%0, %1}, %2;" : "=f"(lo), "=f"(hi) : "l"(v));
}

// d = a * b + c (packed 2x f32). volatile: preserve source order so the
// shared-c groups stay consecutive for the operand reuse cache.
__device__ __forceinline__ uint64_t fma2v(uint64_t a, uint64_t b, uint64_t c) {
    uint64_t d;
    asm volatile("fma.rn.f32x2 %0, %1, %2, %3;" : "=l"(d) : "l"(a), "l"(b), "l"(c));
    return d;
}

// cC[p]    = dup2(coef[p])      (numerator)
// cC[64+p] = dup2(coef[64+p])   (denominator)
__constant__ uint64_t cC[128];
__device__ uint64_t g_pairs[128];

__global__ void pack_kernel(const float* __restrict__ coef) {
    int i = threadIdx.x;  // 128 threads
    uint32_t u = __float_as_uint(coef[i]);
    g_pairs[i] = (uint64_t)u | ((uint64_t)u << 32);
}

static constexpr int THREADS = 128;
static constexpr int ELEMS_PER_THREAD = 8;                          // 4 f32x2 lanes
static constexpr int ELEMS_PER_BLOCK = THREADS * ELEMS_PER_THREAD;  // 1024
static constexpr int F4_PER_BLOCK = ELEMS_PER_BLOCK / 4;            // 256

__global__ __launch_bounds__(THREADS)
void rational_kernel(const float4* __restrict__ x4,
                     float4* __restrict__ out4)
{
    int tid = threadIdx.x;

    // Two coalesced float4 loads per thread (stride THREADS apart).
    int base = blockIdx.x * F4_PER_BLOCK + tid;
    float4 a = x4[base];
    float4 b = x4[base + THREADS];

    uint64_t xp[4];
    xp[0] = pack2(a.x, a.y);
    xp[1] = pack2(a.z, a.w);
    xp[2] = pack2(b.x, b.y);
    xp[3] = pack2(b.z, b.w);

    uint64_t accN[4], accD[4];
    {
        uint64_t n63 = cC[63];
        uint64_t m63 = cC[127];
#pragma unroll
        for (int j = 0; j < 4; j++) { accN[j] = n63; accD[j] = m63; }
    }

    // Dual Horner, fully unrolled. Per step: 4 FMAs sharing cn, then 4
    // sharing cm (reversed j so xp[3] is also consecutive in slot 2).
#pragma unroll
    for (int p = 62; p >= 0; p--) {
        uint64_t cn = cC[p];
        uint64_t cm = cC[64 + p];
        accN[0] = fma2v(accN[0], xp[0], cn);
        accN[1] = fma2v(accN[1], xp[1], cn);
        accN[2] = fma2v(accN[2], xp[2], cn);
        accN[3] = fma2v(accN[3], xp[3], cn);
        accD[3] = fma2v(accD[3], xp[3], cm);
        accD[2] = fma2v(accD[2], xp[2], cm);
        accD[1] = fma2v(accD[1], xp[1], cm);
        accD[0] = fma2v(accD[0], xp[0], cm);
    }

    // Epilogue: den = x * Q(x); out = P / (|den| + 1).
    float4 o[2];
    float* of = reinterpret_cast<float*>(o);
#pragma unroll
    for (int j = 0; j < 4; j++) {
        float nlo, nhi, dlo, dhi, xlo, xhi;
        unpack2(accN[j], nlo, nhi);
        unpack2(accD[j], dlo, dhi);
        unpack2(xp[j],   xlo, xhi);
        of[2 * j]     = __fdividef(nlo, fabsf(xlo * dlo) + 1.0f);
        of[2 * j + 1] = __fdividef(nhi, fabsf(xhi * dhi) + 1.0f);
    }

    out4[base] = o[0];
    out4[base + THREADS] = o[1];
}

extern "C" void kernel_launch(void* const* d_in, const int* in_sizes, int n_in,
                              void* d_out, int out_size) {
    const float* x    = (const float*)d_in[0];
    const float* coef = (const float*)d_in[1];
    float* out        = (float*)d_out;

    int N = in_sizes[0];                 // 4194304, divisible by 1024
    int blocks = N / ELEMS_PER_BLOCK;    // 4096

    // 1) Duplicate each coefficient into both halves of a u64 pair.
    pack_kernel<<<1, 128>>>(coef);

    // 2) Stage the packed pairs into constant memory (D2D memcpy node).
    void* src = nullptr;
    cudaGetSymbolAddress(&src, g_pairs);
    cudaMemcpyToSymbolAsync(cC, src, 128 * sizeof(uint64_t), 0,
                            cudaMemcpyDeviceToDevice, 0);

    // 3) Main compute kernel.
    rational_kernel<<<blocks, THREADS>>>(
        (const float4*)x, (float4*)out);
}